// round 4
// baseline (speedup 1.0000x reference)
#include <cuda_runtime.h>
#include <math.h>

#define B_  4
#define T_  4096
#define D_  1024
#define DH_ 64
#define NROW (B_ * T_)
#define CH_ 16
#define NITEM 640                      // attn work items
#define PITEM 768                      // proj work items: 256 tiles x 3

__device__ float g_Q[NROW * DH_];
__device__ float g_K[NROW * DH_];
__device__ float g_V[NROW * DH_];
__device__ unsigned int g_ctr;         // attn queue
__device__ unsigned int g_ctrp;        // proj queue
__device__ float g_po[256 * 4 * 4096];
__device__ float g_pml[256 * 4 * 128];

#define FMA2(d, a, b) asm("fma.rn.f32x2 %0, %1, %2, %0;" : "+l"(d) : "l"(a), "l"(b))
#define MUL2(d, a, b) asm("mul.rn.f32x2 %0, %1, %2;" : "=l"(d) : "l"(a), "l"(b))

static __device__ __forceinline__ unsigned long long pk2(float a, float b) {
    unsigned long long r;
    asm("mov.b64 %0, {%1, %2};" : "=l"(r) : "f"(a), "f"(b));
    return r;
}
static __device__ __forceinline__ float unpk_sum(unsigned long long v) {
    float lo, hi;
    asm("mov.b64 {%0, %1}, %2;" : "=f"(lo), "=f"(hi) : "l"(v));
    return lo + hi;
}

// ---------------------------------------------------------------------------
// Kernel 1: persistent QKV projection. Item = (which, 64-row tile).
// smem holds PRE-PAIRED u64 operands: hot loop is pure LDS + FFMA2.
// ---------------------------------------------------------------------------
__global__ __launch_bounds__(256) void proj_kernel(
    const float* __restrict__ x,
    const float* __restrict__ Wq,
    const float* __restrict__ Wk,
    const float* __restrict__ Wv)
{
    __shared__ unsigned long long xs2[64][18];   // [row][k-pair], pad keeps 16B align
    __shared__ unsigned long long ws2[16][66];   // [k-pair][h]
    __shared__ int s_item;

    const int tid = threadIdx.x;
    const int tx = tid & 15, ty = tid >> 4;
    const int r0 = ty * 4, c0 = tx * 4;

    for (;;) {
        if (tid == 0) s_item = atomicAdd(&g_ctrp, 1);
        __syncthreads();
        const int n = s_item;
        if (n >= PITEM) return;
        const int which = n >> 8;          // 0..2
        const int tile  = n & 255;         // 0..255
        const float* W  = (which == 0) ? Wq : (which == 1) ? Wk : Wv;
        float* out      = (which == 0) ? g_Q : (which == 1) ? g_K : g_V;
        const int row_base = tile * 64;

        unsigned long long acc2[4][4];
        #pragma unroll
        for (int i = 0; i < 4; i++)
            #pragma unroll
            for (int j = 0; j < 4; j++) acc2[i][j] = 0ull;

        for (int k0 = 0; k0 < D_; k0 += 32) {
            // x tile 64x32 -> paired u64 (2 float4 per thread)
            #pragma unroll
            for (int p = tid; p < 512; p += 256) {
                int r = p >> 3, c4 = (p & 7) * 4;
                float4 v = *reinterpret_cast<const float4*>(
                    &x[(size_t)(row_base + r) * D_ + k0 + c4]);
                ulonglong2 u;
                u.x = pk2(v.x, v.y); u.y = pk2(v.z, v.w);
                *reinterpret_cast<ulonglong2*>(&xs2[r][c4 >> 1]) = u;
            }
            // W tile 32x64 -> paired u64 (1 unit per thread)
            {
                int kp = tid >> 4, c4 = (tid & 15) * 4;
                float4 va = *reinterpret_cast<const float4*>(
                    &W[(size_t)(k0 + 2 * kp) * DH_ + c4]);
                float4 vb = *reinterpret_cast<const float4*>(
                    &W[(size_t)(k0 + 2 * kp + 1) * DH_ + c4]);
                ulonglong2 u0, u1;
                u0.x = pk2(va.x, vb.x); u0.y = pk2(va.y, vb.y);
                u1.x = pk2(va.z, vb.z); u1.y = pk2(va.w, vb.w);
                *reinterpret_cast<ulonglong2*>(&ws2[kp][c4])     = u0;
                *reinterpret_cast<ulonglong2*>(&ws2[kp][c4 + 2]) = u1;
            }
            __syncthreads();

            #pragma unroll 4
            for (int kp = 0; kp < 16; kp++) {
                ulonglong2 bA = *reinterpret_cast<const ulonglong2*>(&ws2[kp][c0]);
                ulonglong2 bB = *reinterpret_cast<const ulonglong2*>(&ws2[kp][c0 + 2]);
                #pragma unroll
                for (int i = 0; i < 4; i++) {
                    unsigned long long a = xs2[r0 + i][kp];
                    FMA2(acc2[i][0], a, bA.x);
                    FMA2(acc2[i][1], a, bA.y);
                    FMA2(acc2[i][2], a, bB.x);
                    FMA2(acc2[i][3], a, bB.y);
                }
            }
            __syncthreads();
        }

        #pragma unroll
        for (int i = 0; i < 4; i++) {
            float4 r;
            r.x = unpk_sum(acc2[i][0]); r.y = unpk_sum(acc2[i][1]);
            r.z = unpk_sum(acc2[i][2]); r.w = unpk_sum(acc2[i][3]);
            *reinterpret_cast<float4*>(
                &out[(size_t)(row_base + r0 + i) * DH_ + c0]) = r;
        }
    }
}

// ---------------------------------------------------------------------------
// Kernel 2: persistent causal flash attention with KV-split (as R3),
// Q pre-scaled by d^-0.5 at load.
// ---------------------------------------------------------------------------
#define SROW 68

__global__ __launch_bounds__(256, 2) void attn_kernel(float* __restrict__ out)
{
    extern __shared__ float sm[];
    float (*Qs)[SROW] = (float(*)[SROW])(sm);
    float (*Ks)[SROW] = (float(*)[SROW])(sm + 64 * SROW);
    float (*Vs)[SROW] = (float(*)[SROW])(sm + 2 * 64 * SROW);
    float (*Ss)[SROW] = (float(*)[SROW])(sm + 3 * 64 * SROW);
    __shared__ int s_item;

    const int tid = threadIdx.x;
    const int tx = tid & 15, ty = tid >> 4;
    const int r0 = ty * 4, c0 = tx * 4;
    const float scale = 0.03125f;   // 1024^-0.5

    for (;;) {
        if (tid == 0) s_item = atomicAdd(&g_ctr, 1);
        __syncthreads();
        const int n = s_item;
        if (n >= NITEM) return;
        const int b = n & 3;
        int idx = n >> 2;
        int qt = 63, rem = idx;
        while (rem >= ((qt + 16) >> 4)) { rem -= (qt + 16) >> 4; qt--; }
        const int ch = rem;
        const int nc = (qt + 16) >> 4;
        const int t0 = ch * CH_;
        const int t1 = (t0 + CH_ < qt + 1) ? (t0 + CH_) : (qt + 1);

        const float* Qg = g_Q + (size_t)(b * T_ + qt * 64) * DH_;
        #pragma unroll
        for (int p = tid; p < 1024; p += 256) {
            int r = p >> 4, c4 = (p & 15) * 4;
            float4 v = *reinterpret_cast<const float4*>(&Qg[r * DH_ + c4]);
            Qs[r][c4 + 0] = v.x * scale; Qs[r][c4 + 1] = v.y * scale;
            Qs[r][c4 + 2] = v.z * scale; Qs[r][c4 + 3] = v.w * scale;
        }

        float m[4], l[4];
        unsigned long long o2[4][4];
        #pragma unroll
        for (int i = 0; i < 4; i++) {
            m[i] = -INFINITY; l[i] = 0.f;
            #pragma unroll
            for (int j = 0; j < 4; j++) o2[i][j] = 0ull;
        }
        __syncthreads();

        for (int t = t0; t < t1; t++) {
            const float* Kg = g_K + (size_t)(b * T_ + t * 64) * DH_;
            const float* Vg = g_V + (size_t)(b * T_ + t * 64) * DH_;
            #pragma unroll
            for (int p = tid; p < 1024; p += 256) {
                int r = p >> 4, c4 = (p & 15) * 4;
                float4 v = *reinterpret_cast<const float4*>(&Kg[r * DH_ + c4]);
                Ks[r][c4 + 0] = v.x; Ks[r][c4 + 1] = v.y;
                Ks[r][c4 + 2] = v.z; Ks[r][c4 + 3] = v.w;
                float4 w = *reinterpret_cast<const float4*>(&Vg[r * DH_ + c4]);
                Vs[r][c4 + 0] = w.x; Vs[r][c4 + 1] = w.y;
                Vs[r][c4 + 2] = w.z; Vs[r][c4 + 3] = w.w;
            }
            __syncthreads();

            unsigned long long s2[4][4];
            #pragma unroll
            for (int i = 0; i < 4; i++)
                #pragma unroll
                for (int j = 0; j < 4; j++) s2[i][j] = 0ull;

            #pragma unroll 4
            for (int k4 = 0; k4 < 16; k4++) {
                ulonglong2 q2[4], k2[4];
                #pragma unroll
                for (int i = 0; i < 4; i++)
                    q2[i] = *reinterpret_cast<const ulonglong2*>(&Qs[r0 + i][k4 * 4]);
                #pragma unroll
                for (int j = 0; j < 4; j++)
                    k2[j] = *reinterpret_cast<const ulonglong2*>(&Ks[tx + 16 * j][k4 * 4]);
                #pragma unroll
                for (int i = 0; i < 4; i++)
                    #pragma unroll
                    for (int j = 0; j < 4; j++) {
                        FMA2(s2[i][j], q2[i].x, k2[j].x);
                        FMA2(s2[i][j], q2[i].y, k2[j].y);
                    }
            }

            const bool diag = (t == qt);

            #pragma unroll
            for (int i = 0; i < 4; i++) {
                float sv[4];
                float mt = -INFINITY;
                #pragma unroll
                for (int j = 0; j < 4; j++) {
                    float v = unpk_sum(s2[i][j]);
                    if (diag && (tx + 16 * j) > (r0 + i)) v = -1e30f;
                    sv[j] = v;
                    mt = fmaxf(mt, v);
                }
                #pragma unroll
                for (int off = 1; off < 16; off <<= 1)
                    mt = fmaxf(mt, __shfl_xor_sync(0xffffffffu, mt, off));

                float mn    = fmaxf(m[i], mt);
                float alpha = __expf(m[i] - mn);
                m[i] = mn;

                float rs = 0.f;
                #pragma unroll
                for (int j = 0; j < 4; j++) {
                    float p = __expf(sv[j] - mn);
                    Ss[r0 + i][tx + 16 * j] = p;
                    rs += p;
                }
                #pragma unroll
                for (int off = 1; off < 16; off <<= 1)
                    rs += __shfl_xor_sync(0xffffffffu, rs, off);

                l[i] = l[i] * alpha + rs;
                unsigned long long a2 = pk2(alpha, alpha);
                #pragma unroll
                for (int j = 0; j < 4; j++) MUL2(o2[i][j], o2[i][j], a2);
            }
            __syncthreads();

            #pragma unroll 4
            for (int k4 = 0; k4 < 16; k4++) {
                float4 v0 = *reinterpret_cast<const float4*>(&Vs[k4 * 4 + 0][c0]);
                float4 v1 = *reinterpret_cast<const float4*>(&Vs[k4 * 4 + 1][c0]);
                float4 v2 = *reinterpret_cast<const float4*>(&Vs[k4 * 4 + 2][c0]);
                float4 v3 = *reinterpret_cast<const float4*>(&Vs[k4 * 4 + 3][c0]);
                ulonglong2 p2[4];
                #pragma unroll
                for (int i = 0; i < 4; i++)
                    p2[i] = *reinterpret_cast<const ulonglong2*>(&Ss[r0 + i][k4 * 4]);

                unsigned long long va0 = pk2(v0.x, v1.x), va1 = pk2(v2.x, v3.x);
                unsigned long long vb0 = pk2(v0.y, v1.y), vb1 = pk2(v2.y, v3.y);
                unsigned long long vc0 = pk2(v0.z, v1.z), vc1 = pk2(v2.z, v3.z);
                unsigned long long vd0 = pk2(v0.w, v1.w), vd1 = pk2(v2.w, v3.w);

                #pragma unroll
                for (int i = 0; i < 4; i++) {
                    FMA2(o2[i][0], p2[i].x, va0); FMA2(o2[i][0], p2[i].y, va1);
                    FMA2(o2[i][1], p2[i].x, vb0); FMA2(o2[i][1], p2[i].y, vb1);
                    FMA2(o2[i][2], p2[i].x, vc0); FMA2(o2[i][2], p2[i].y, vc1);
                    FMA2(o2[i][3], p2[i].x, vd0); FMA2(o2[i][3], p2[i].y, vd1);
                }
            }
            __syncthreads();
        }

        if (nc == 1) {
            float* Og = out + (size_t)(b * T_ + qt * 64) * DH_;
            #pragma unroll
            for (int i = 0; i < 4; i++) {
                float inv = 1.0f / l[i];
                float4 r;
                r.x = unpk_sum(o2[i][0]) * inv;
                r.y = unpk_sum(o2[i][1]) * inv;
                r.z = unpk_sum(o2[i][2]) * inv;
                r.w = unpk_sum(o2[i][3]) * inv;
                *reinterpret_cast<float4*>(&Og[(r0 + i) * DH_ + c0]) = r;
            }
        } else {
            const int pidx = (b * 64 + qt) * 4 + ch;
            float* po = g_po + (size_t)pidx * 4096;
            #pragma unroll
            for (int i = 0; i < 4; i++) {
                float4 r;
                r.x = unpk_sum(o2[i][0]);
                r.y = unpk_sum(o2[i][1]);
                r.z = unpk_sum(o2[i][2]);
                r.w = unpk_sum(o2[i][3]);
                *reinterpret_cast<float4*>(&po[(r0 + i) * 64 + c0]) = r;
                if (tx == 0) {
                    g_pml[pidx * 128 + (r0 + i)]      = m[i];
                    g_pml[pidx * 128 + 64 + (r0 + i)] = l[i];
                }
            }
        }
    }
}

// ---------------------------------------------------------------------------
// Kernel 3: merge partials (qt >= 16) + reset queues for next graph replay.
// ---------------------------------------------------------------------------
__global__ __launch_bounds__(256) void merge_kernel(float* __restrict__ out)
{
    if (blockIdx.x == 0 && threadIdx.x == 0) { g_ctr = 0; g_ctrp = 0; }

    const int bid = blockIdx.x;
    const int b  = bid & 3;
    const int qt = 16 + (bid >> 2);
    const int nc = (qt + 16) >> 4;
    const int tid = threadIdx.x;
    const int r  = tid >> 2;
    const int cg = (tid & 3) << 4;

    const int base = (b * 64 + qt) * 4;

    float mv[4], lv[4];
    float ms = -INFINITY;
    #pragma unroll
    for (int c = 0; c < 4; c++)
        if (c < nc) {
            mv[c] = g_pml[(base + c) * 128 + r];
            lv[c] = g_pml[(base + c) * 128 + 64 + r];
            ms = fmaxf(ms, mv[c]);
        }

    float acc[16];
    #pragma unroll
    for (int j = 0; j < 16; j++) acc[j] = 0.f;
    float lsum = 0.f;

    #pragma unroll
    for (int c = 0; c < 4; c++)
        if (c < nc) {
            float w = __expf(mv[c] - ms);
            lsum += lv[c] * w;
            const float* po = g_po + (size_t)(base + c) * 4096 + r * 64 + cg;
            #pragma unroll
            for (int j4 = 0; j4 < 4; j4++) {
                float4 v = *reinterpret_cast<const float4*>(po + j4 * 4);
                acc[j4 * 4 + 0] = fmaf(v.x, w, acc[j4 * 4 + 0]);
                acc[j4 * 4 + 1] = fmaf(v.y, w, acc[j4 * 4 + 1]);
                acc[j4 * 4 + 2] = fmaf(v.z, w, acc[j4 * 4 + 2]);
                acc[j4 * 4 + 3] = fmaf(v.w, w, acc[j4 * 4 + 3]);
            }
        }

    const float inv = 1.0f / lsum;
    float* og = out + (size_t)(b * T_ + qt * 64 + r) * DH_ + cg;
    #pragma unroll
    for (int j4 = 0; j4 < 4; j4++) {
        float4 v;
        v.x = acc[j4 * 4 + 0] * inv;
        v.y = acc[j4 * 4 + 1] * inv;
        v.z = acc[j4 * 4 + 2] * inv;
        v.w = acc[j4 * 4 + 3] * inv;
        *reinterpret_cast<float4*>(og + j4 * 4) = v;
    }
}

// ---------------------------------------------------------------------------
extern "C" void kernel_launch(void* const* d_in, const int* in_sizes, int n_in,
                              void* d_out, int out_size)
{
    const float* x  = (const float*)d_in[0];
    const float* Wq = (const float*)d_in[1];
    const float* Wk = (const float*)d_in[2];
    const float* Wv = (const float*)d_in[3];
    float* out = (float*)d_out;

    proj_kernel<<<444, 256>>>(x, Wq, Wk, Wv);

    size_t smem = (size_t)4 * 64 * SROW * sizeof(float);
    cudaFuncSetAttribute(attn_kernel,
                         cudaFuncAttributeMaxDynamicSharedMemorySize,
                         (int)smem);
    attn_kernel<<<296, 256, smem>>>(out);

    merge_kernel<<<192, 256>>>(out);
}

// round 9
// speedup vs baseline: 1.3467x; 1.3467x over previous
#include <cuda_runtime.h>
#include <cuda_bf16.h>
#include <math.h>

#define B_  4
#define T_  4096
#define D_  1024
#define DH_ 64
#define NROW (B_ * T_)
#define CH_ 16
#define NITEM 640

__device__ float g_Q[NROW * DH_];
__device__ float g_K[NROW * DH_];
__device__ float g_V[NROW * DH_];
__device__ unsigned int g_ctr;
__device__ float g_po[256 * 4 * 4096];
__device__ float g_pml[256 * 4 * 128];
// W transposed to K-major [3][64 h][1024 d], split hi/lo bf16
__device__ __align__(16) unsigned short g_Wth[3 * 64 * 1024];
__device__ __align__(16) unsigned short g_Wtl[3 * 64 * 1024];

// ---------------- fp32x2 helpers (attn path) ----------------
#define FMA2(d, a, b) asm("fma.rn.f32x2 %0, %1, %2, %0;" : "+l"(d) : "l"(a), "l"(b))
#define MUL2(d, a, b) asm("mul.rn.f32x2 %0, %1, %2;" : "=l"(d) : "l"(a), "l"(b))
static __device__ __forceinline__ unsigned long long pk2(float a, float b) {
    unsigned long long r;
    asm("mov.b64 %0, {%1, %2};" : "=l"(r) : "f"(a), "f"(b));
    return r;
}
static __device__ __forceinline__ float unpk_sum(unsigned long long v) {
    float lo, hi;
    asm("mov.b64 {%0, %1}, %2;" : "=f"(lo), "=f"(hi) : "l"(v));
    return lo + hi;
}

// round-to-nearest fp32 -> (bf16 hi, bf16 lo) split, packed pairwise:
// h = (bf16(a) | bf16(b)<<16), l = (bf16(a-hi a) | bf16(b-hi b)<<16)
static __device__ __forceinline__ void split2(float a, float b,
                                              unsigned& h, unsigned& l) {
    unsigned ua = __float_as_uint(a), ub = __float_as_uint(b);
    unsigned ra = (ua + 0x7FFFu + ((ua >> 16) & 1u)) & 0xFFFF0000u;
    unsigned rb = (ub + 0x7FFFu + ((ub >> 16) & 1u)) & 0xFFFF0000u;
    h = (ra >> 16) | (rb & 0xFFFF0000u);
    float la = a - __uint_as_float(ra);
    float lb = b - __uint_as_float(rb);
    unsigned va = __float_as_uint(la), vb = __float_as_uint(lb);
    unsigned rla = (va + 0x7FFFu + ((va >> 16) & 1u));
    unsigned rlb = (vb + 0x7FFFu + ((vb >> 16) & 1u)) & 0xFFFF0000u;
    l = (rla >> 16) | rlb;
}

// bf16 mma: D(f32) += A(16x16 bf16, row) * B(16x8 bf16, col)
#define MMA_BF16(d, a0, a1, a2, a3, b0, b1)                                 \
    asm volatile("mma.sync.aligned.m16n8k16.row.col.f32.bf16.bf16.f32 "     \
        "{%0,%1,%2,%3}, {%4,%5,%6,%7}, {%8,%9}, {%0,%1,%2,%3};"             \
        : "+f"((d)[0]), "+f"((d)[1]), "+f"((d)[2]), "+f"((d)[3])            \
        : "r"(a0), "r"(a1), "r"(a2), "r"(a3), "r"(b0), "r"(b1))

// ---------------------------------------------------------------------------
// Kernel 0: transpose + bf16-split W -> g_Wth/g_Wtl [3][64 h][1024 d] K-major.
// ---------------------------------------------------------------------------
__global__ __launch_bounds__(256) void wsplit_kernel(
    const float* __restrict__ Wq,
    const float* __restrict__ Wk,
    const float* __restrict__ Wv)
{
    const int mat = blockIdx.x;
    const int d0  = blockIdx.y * 64;
    const float* W = (mat == 0) ? Wq : (mat == 1) ? Wk : Wv;

    __shared__ float ts[64][65];
    const int tid = threadIdx.x;
    #pragma unroll
    for (int rep = 0; rep < 16; rep++) {
        int idx = rep * 256 + tid;
        ts[idx >> 6][idx & 63] = W[(size_t)(d0 + (idx >> 6)) * 64 + (idx & 63)];
    }
    __syncthreads();

    const int h  = tid >> 2;
    const int dg = (tid & 3) * 16;
    unsigned* oh = reinterpret_cast<unsigned*>(g_Wth);
    unsigned* ol = reinterpret_cast<unsigned*>(g_Wtl);
    #pragma unroll
    for (int j = 0; j < 8; j++) {
        unsigned hv, lv;
        split2(ts[dg + 2 * j][h], ts[dg + 2 * j + 1][h], hv, lv);
        int i32 = ((mat * 64 + h) * 1024 + d0 + dg + 2 * j) >> 1;
        oh[i32] = hv;
        ol[i32] = lv;
    }
}

// ---------------------------------------------------------------------------
// Kernel 1: QKV projection via mma.sync bf16 with hi/lo error compensation.
// Grid (256, 3): one block = 64 rows x 64 h of one matrix.
// Block 256 = 8 warps: warp grid 4(M) x 2(N) -> warp tile 16 rows x 32 cols.
// Accumulate hi*hi + hi*lo + lo*hi in fp32.
// ---------------------------------------------------------------------------
#define SH 72    // smem stride in halves (bank-conflict-free: 4g+tig pattern)

__global__ __launch_bounds__(256, 2) void proj_mma_kernel(
    const float* __restrict__ x)
{
    __shared__ unsigned short Ah[64 * SH], Al[64 * SH];
    __shared__ unsigned short Bh[64 * SH], Bl[64 * SH];

    const int tid  = threadIdx.x;
    const int wid  = tid >> 5, lane = tid & 31;
    const int g    = lane >> 2, tig = lane & 3;
    const int wm   = (wid & 3) * 16;   // warp M offset
    const int wn   = (wid >> 2) * 32;  // warp N offset
    const int mat  = blockIdx.y;
    const int row_base = blockIdx.x * 64;

    const unsigned short* Wh = g_Wth + (size_t)mat * 64 * 1024;
    const unsigned short* Wl = g_Wtl + (size_t)mat * 64 * 1024;

    const int lr = tid >> 2;          // load row (A) / h row (B)
    const int lq = (tid & 3) * 16;    // 16-element k group

    float acc[4][4];
    #pragma unroll
    for (int nt = 0; nt < 4; nt++)
        #pragma unroll
        for (int r = 0; r < 4; r++) acc[nt][r] = 0.f;

    for (int c = 0; c < 16; c++) {
        const int k0 = c * 64;
        // ---- A chunk: 64 rows x 64 k fp32 -> hi/lo bf16 smem ----
        {
            const float4* xp = reinterpret_cast<const float4*>(
                x + (size_t)(row_base + lr) * D_ + k0 + lq);
            float4 v0 = xp[0], v1 = xp[1], v2 = xp[2], v3 = xp[3];
            uint4 hv, lv, hv2, lv2;
            split2(v0.x, v0.y, hv.x, lv.x);  split2(v0.z, v0.w, hv.y, lv.y);
            split2(v1.x, v1.y, hv.z, lv.z);  split2(v1.z, v1.w, hv.w, lv.w);
            split2(v2.x, v2.y, hv2.x, lv2.x); split2(v2.z, v2.w, hv2.y, lv2.y);
            split2(v3.x, v3.y, hv2.z, lv2.z); split2(v3.z, v3.w, hv2.w, lv2.w);
            unsigned short* pa = &Ah[lr * SH + lq];
            unsigned short* pl = &Al[lr * SH + lq];
            *reinterpret_cast<uint4*>(pa)     = hv;
            *reinterpret_cast<uint4*>(pa + 8) = hv2;
            *reinterpret_cast<uint4*>(pl)     = lv;
            *reinterpret_cast<uint4*>(pl + 8) = lv2;
        }
        // ---- B chunk: 64 h x 64 k bf16 hi/lo (already split) ----
        {
            const uint4* bh = reinterpret_cast<const uint4*>(
                Wh + (size_t)lr * 1024 + k0 + lq);
            const uint4* bl = reinterpret_cast<const uint4*>(
                Wl + (size_t)lr * 1024 + k0 + lq);
            unsigned short* pb = &Bh[lr * SH + lq];
            unsigned short* pl = &Bl[lr * SH + lq];
            *reinterpret_cast<uint4*>(pb)     = bh[0];
            *reinterpret_cast<uint4*>(pb + 8) = bh[1];
            *reinterpret_cast<uint4*>(pl)     = bl[0];
            *reinterpret_cast<uint4*>(pl + 8) = bl[1];
        }
        __syncthreads();

        #pragma unroll
        for (int ks = 0; ks < 4; ks++) {
            const int wb = ks * 8;   // 32-bit word offset within row
            // A fragments (hi & lo)
            const int ra = (wm + g) * SH;
            unsigned ah0 = *reinterpret_cast<const unsigned*>(&Ah[ra + (wb + tig) * 2]);
            unsigned ah1 = *reinterpret_cast<const unsigned*>(&Ah[ra + 8 * SH + (wb + tig) * 2]);
            unsigned ah2 = *reinterpret_cast<const unsigned*>(&Ah[ra + (wb + 4 + tig) * 2]);
            unsigned ah3 = *reinterpret_cast<const unsigned*>(&Ah[ra + 8 * SH + (wb + 4 + tig) * 2]);
            unsigned al0 = *reinterpret_cast<const unsigned*>(&Al[ra + (wb + tig) * 2]);
            unsigned al1 = *reinterpret_cast<const unsigned*>(&Al[ra + 8 * SH + (wb + tig) * 2]);
            unsigned al2 = *reinterpret_cast<const unsigned*>(&Al[ra + (wb + 4 + tig) * 2]);
            unsigned al3 = *reinterpret_cast<const unsigned*>(&Al[ra + 8 * SH + (wb + 4 + tig) * 2]);

            #pragma unroll
            for (int nt = 0; nt < 4; nt++) {
                const int rb = (wn + nt * 8 + g) * SH;
                unsigned bh0 = *reinterpret_cast<const unsigned*>(&Bh[rb + (wb + tig) * 2]);
                unsigned bh1 = *reinterpret_cast<const unsigned*>(&Bh[rb + (wb + 4 + tig) * 2]);
                unsigned bl0 = *reinterpret_cast<const unsigned*>(&Bl[rb + (wb + tig) * 2]);
                unsigned bl1 = *reinterpret_cast<const unsigned*>(&Bl[rb + (wb + 4 + tig) * 2]);
                MMA_BF16(acc[nt], ah0, ah1, ah2, ah3, bh0, bh1);
                MMA_BF16(acc[nt], ah0, ah1, ah2, ah3, bl0, bl1);
                MMA_BF16(acc[nt], al0, al1, al2, al3, bh0, bh1);
            }
        }
        __syncthreads();
    }

    // epilogue: c0/c1 -> (row, 2tig), c2/c3 -> (row+8, 2tig)
    float* op = (mat == 0) ? g_Q : (mat == 1) ? g_K : g_V;
    const int row0 = row_base + wm + g;
    #pragma unroll
    for (int nt = 0; nt < 4; nt++) {
        const int col = wn + nt * 8 + 2 * tig;
        float2 v0 = make_float2(acc[nt][0], acc[nt][1]);
        float2 v1 = make_float2(acc[nt][2], acc[nt][3]);
        *reinterpret_cast<float2*>(&op[(size_t)row0 * DH_ + col])       = v0;
        *reinterpret_cast<float2*>(&op[(size_t)(row0 + 8) * DH_ + col]) = v1;
    }
}

// ---------------------------------------------------------------------------
// Kernel 2: persistent causal flash attention with KV-split (proven R3/R4).
// ---------------------------------------------------------------------------
#define SROW 68

__global__ __launch_bounds__(256, 2) void attn_kernel(float* __restrict__ out)
{
    extern __shared__ float sm[];
    float (*Qs)[SROW] = (float(*)[SROW])(sm);
    float (*Ks)[SROW] = (float(*)[SROW])(sm + 64 * SROW);
    float (*Vs)[SROW] = (float(*)[SROW])(sm + 2 * 64 * SROW);
    float (*Ss)[SROW] = (float(*)[SROW])(sm + 3 * 64 * SROW);
    __shared__ int s_item;

    const int tid = threadIdx.x;
    const int tx = tid & 15, ty = tid >> 4;
    const int r0 = ty * 4, c0 = tx * 4;
    const float scale = 0.03125f;

    for (;;) {
        if (tid == 0) s_item = atomicAdd(&g_ctr, 1);
        __syncthreads();
        const int n = s_item;
        if (n >= NITEM) return;
        const int b = n & 3;
        int idx = n >> 2;
        int qt = 63, rem = idx;
        while (rem >= ((qt + 16) >> 4)) { rem -= (qt + 16) >> 4; qt--; }
        const int ch = rem;
        const int nc = (qt + 16) >> 4;
        const int t0 = ch * CH_;
        const int t1 = (t0 + CH_ < qt + 1) ? (t0 + CH_) : (qt + 1);

        const float* Qg = g_Q + (size_t)(b * T_ + qt * 64) * DH_;
        #pragma unroll
        for (int p = tid; p < 1024; p += 256) {
            int r = p >> 4, c4 = (p & 15) * 4;
            float4 v = *reinterpret_cast<const float4*>(&Qg[r * DH_ + c4]);
            Qs[r][c4 + 0] = v.x * scale; Qs[r][c4 + 1] = v.y * scale;
            Qs[r][c4 + 2] = v.z * scale; Qs[r][c4 + 3] = v.w * scale;
        }

        float m[4], l[4];
        unsigned long long o2[4][4];
        #pragma unroll
        for (int i = 0; i < 4; i++) {
            m[i] = -INFINITY; l[i] = 0.f;
            #pragma unroll
            for (int j = 0; j < 4; j++) o2[i][j] = 0ull;
        }
        __syncthreads();

        for (int t = t0; t < t1; t++) {
            const float* Kg = g_K + (size_t)(b * T_ + t * 64) * DH_;
            const float* Vg = g_V + (size_t)(b * T_ + t * 64) * DH_;
            #pragma unroll
            for (int p = tid; p < 1024; p += 256) {
                int r = p >> 4, c4 = (p & 15) * 4;
                float4 v = *reinterpret_cast<const float4*>(&Kg[r * DH_ + c4]);
                Ks[r][c4 + 0] = v.x; Ks[r][c4 + 1] = v.y;
                Ks[r][c4 + 2] = v.z; Ks[r][c4 + 3] = v.w;
                float4 w = *reinterpret_cast<const float4*>(&Vg[r * DH_ + c4]);
                Vs[r][c4 + 0] = w.x; Vs[r][c4 + 1] = w.y;
                Vs[r][c4 + 2] = w.z; Vs[r][c4 + 3] = w.w;
            }
            __syncthreads();

            unsigned long long s2[4][4];
            #pragma unroll
            for (int i = 0; i < 4; i++)
                #pragma unroll
                for (int j = 0; j < 4; j++) s2[i][j] = 0ull;

            #pragma unroll 4
            for (int k4 = 0; k4 < 16; k4++) {
                ulonglong2 q2[4], k2[4];
                #pragma unroll
                for (int i = 0; i < 4; i++)
                    q2[i] = *reinterpret_cast<const ulonglong2*>(&Qs[r0 + i][k4 * 4]);
                #pragma unroll
                for (int j = 0; j < 4; j++)
                    k2[j] = *reinterpret_cast<const ulonglong2*>(&Ks[tx + 16 * j][k4 * 4]);
                #pragma unroll
                for (int i = 0; i < 4; i++)
                    #pragma unroll
                    for (int j = 0; j < 4; j++) {
                        FMA2(s2[i][j], q2[i].x, k2[j].x);
                        FMA2(s2[i][j], q2[i].y, k2[j].y);
                    }
            }

            const bool diag = (t == qt);

            #pragma unroll
            for (int i = 0; i < 4; i++) {
                float sv[4];
                float mt = -INFINITY;
                #pragma unroll
                for (int j = 0; j < 4; j++) {
                    float v = unpk_sum(s2[i][j]);
                    if (diag && (tx + 16 * j) > (r0 + i)) v = -1e30f;
                    sv[j] = v;
                    mt = fmaxf(mt, v);
                }
                #pragma unroll
                for (int off = 1; off < 16; off <<= 1)
                    mt = fmaxf(mt, __shfl_xor_sync(0xffffffffu, mt, off));

                float mn    = fmaxf(m[i], mt);
                float alpha = __expf(m[i] - mn);
                m[i] = mn;

                float rs = 0.f;
                #pragma unroll
                for (int j = 0; j < 4; j++) {
                    float p = __expf(sv[j] - mn);
                    Ss[r0 + i][tx + 16 * j] = p;
                    rs += p;
                }
                #pragma unroll
                for (int off = 1; off < 16; off <<= 1)
                    rs += __shfl_xor_sync(0xffffffffu, rs, off);

                l[i] = l[i] * alpha + rs;
                unsigned long long a2 = pk2(alpha, alpha);
                #pragma unroll
                for (int j = 0; j < 4; j++) MUL2(o2[i][j], o2[i][j], a2);
            }
            __syncthreads();

            #pragma unroll 4
            for (int k4 = 0; k4 < 16; k4++) {
                float4 v0 = *reinterpret_cast<const float4*>(&Vs[k4 * 4 + 0][c0]);
                float4 v1 = *reinterpret_cast<const float4*>(&Vs[k4 * 4 + 1][c0]);
                float4 v2 = *reinterpret_cast<const float4*>(&Vs[k4 * 4 + 2][c0]);
                float4 v3 = *reinterpret_cast<const float4*>(&Vs[k4 * 4 + 3][c0]);
                ulonglong2 p2[4];
                #pragma unroll
                for (int i = 0; i < 4; i++)
                    p2[i] = *reinterpret_cast<const ulonglong2*>(&Ss[r0 + i][k4 * 4]);

                unsigned long long va0 = pk2(v0.x, v1.x), va1 = pk2(v2.x, v3.x);
                unsigned long long vb0 = pk2(v0.y, v1.y), vb1 = pk2(v2.y, v3.y);
                unsigned long long vc0 = pk2(v0.z, v1.z), vc1 = pk2(v2.z, v3.z);
                unsigned long long vd0 = pk2(v0.w, v1.w), vd1 = pk2(v2.w, v3.w);

                #pragma unroll
                for (int i = 0; i < 4; i++) {
                    FMA2(o2[i][0], p2[i].x, va0); FMA2(o2[i][0], p2[i].y, va1);
                    FMA2(o2[i][1], p2[i].x, vb0); FMA2(o2[i][1], p2[i].y, vb1);
                    FMA2(o2[i][2], p2[i].x, vc0); FMA2(o2[i][2], p2[i].y, vc1);
                    FMA2(o2[i][3], p2[i].x, vd0); FMA2(o2[i][3], p2[i].y, vd1);
                }
            }
            __syncthreads();
        }

        if (nc == 1) {
            float* Og = out + (size_t)(b * T_ + qt * 64) * DH_;
            #pragma unroll
            for (int i = 0; i < 4; i++) {
                float inv = 1.0f / l[i];
                float4 r;
                r.x = unpk_sum(o2[i][0]) * inv;
                r.y = unpk_sum(o2[i][1]) * inv;
                r.z = unpk_sum(o2[i][2]) * inv;
                r.w = unpk_sum(o2[i][3]) * inv;
                *reinterpret_cast<float4*>(&Og[(r0 + i) * DH_ + c0]) = r;
            }
        } else {
            const int pidx = (b * 64 + qt) * 4 + ch;
            float* po = g_po + (size_t)pidx * 4096;
            #pragma unroll
            for (int i = 0; i < 4; i++) {
                float4 r;
                r.x = unpk_sum(o2[i][0]);
                r.y = unpk_sum(o2[i][1]);
                r.z = unpk_sum(o2[i][2]);
                r.w = unpk_sum(o2[i][3]);
                *reinterpret_cast<float4*>(&po[(r0 + i) * 64 + c0]) = r;
                if (tx == 0) {
                    g_pml[pidx * 128 + (r0 + i)]      = m[i];
                    g_pml[pidx * 128 + 64 + (r0 + i)] = l[i];
                }
            }
        }
    }
}

// ---------------------------------------------------------------------------
// Kernel 3: merge partials + reset attn queue for next graph replay.
// ---------------------------------------------------------------------------
__global__ __launch_bounds__(256) void merge_kernel(float* __restrict__ out)
{
    if (blockIdx.x == 0 && threadIdx.x == 0) g_ctr = 0;

    const int bid = blockIdx.x;
    const int b  = bid & 3;
    const int qt = 16 + (bid >> 2);
    const int nc = (qt + 16) >> 4;
    const int tid = threadIdx.x;
    const int r  = tid >> 2;
    const int cg = (tid & 3) << 4;

    const int base = (b * 64 + qt) * 4;

    float mv[4], lv[4];
    float ms = -INFINITY;
    #pragma unroll
    for (int c = 0; c < 4; c++)
        if (c < nc) {
            mv[c] = g_pml[(base + c) * 128 + r];
            lv[c] = g_pml[(base + c) * 128 + 64 + r];
            ms = fmaxf(ms, mv[c]);
        }

    float acc[16];
    #pragma unroll
    for (int j = 0; j < 16; j++) acc[j] = 0.f;
    float lsum = 0.f;

    #pragma unroll
    for (int c = 0; c < 4; c++)
        if (c < nc) {
            float w = __expf(mv[c] - ms);
            lsum += lv[c] * w;
            const float* po = g_po + (size_t)(base + c) * 4096 + r * 64 + cg;
            #pragma unroll
            for (int j4 = 0; j4 < 4; j4++) {
                float4 v = *reinterpret_cast<const float4*>(po + j4 * 4);
                acc[j4 * 4 + 0] = fmaf(v.x, w, acc[j4 * 4 + 0]);
                acc[j4 * 4 + 1] = fmaf(v.y, w, acc[j4 * 4 + 1]);
                acc[j4 * 4 + 2] = fmaf(v.z, w, acc[j4 * 4 + 2]);
                acc[j4 * 4 + 3] = fmaf(v.w, w, acc[j4 * 4 + 3]);
            }
        }

    const float inv = 1.0f / lsum;
    float* og = out + (size_t)(b * T_ + qt * 64 + r) * DH_ + cg;
    #pragma unroll
    for (int j4 = 0; j4 < 4; j4++) {
        float4 v;
        v.x = acc[j4 * 4 + 0] * inv;
        v.y = acc[j4 * 4 + 1] * inv;
        v.z = acc[j4 * 4 + 2] * inv;
        v.w = acc[j4 * 4 + 3] * inv;
        *reinterpret_cast<float4*>(og + j4 * 4) = v;
    }
}

// ---------------------------------------------------------------------------
extern "C" void kernel_launch(void* const* d_in, const int* in_sizes, int n_in,
                              void* d_out, int out_size)
{
    const float* x  = (const float*)d_in[0];
    const float* Wq = (const float*)d_in[1];
    const float* Wk = (const float*)d_in[2];
    const float* Wv = (const float*)d_in[3];
    float* out = (float*)d_out;

    dim3 gw(3, 16);
    wsplit_kernel<<<gw, 256>>>(Wq, Wk, Wv);

    dim3 gp(256, 3);
    proj_mma_kernel<<<gp, 256>>>(x);

    size_t smem = (size_t)4 * 64 * SROW * sizeof(float);
    cudaFuncSetAttribute(attn_kernel,
                         cudaFuncAttributeMaxDynamicSharedMemorySize,
                         (int)smem);
    attn_kernel<<<296, 256, smem>>>(out);

    merge_kernel<<<192, 256>>>(out);
}

// round 10
// speedup vs baseline: 2.5334x; 1.8812x over previous
#include <cuda_runtime.h>
#include <cuda_bf16.h>
#include <math.h>

#define B_  4
#define T_  4096
#define D_  1024
#define DH_ 64
#define NROW (B_ * T_)
#define NITEM 576            // 4 * sum_{qt=0..31} ceil((2qt+2)/8)

__device__ float g_Q[NROW * DH_];
__device__ float g_K[NROW * DH_];
__device__ float g_V[NROW * DH_];
__device__ unsigned int g_ctr;
// bf16-split operands for attention (built by prep_kernel)
__device__ unsigned g_Qth[NROW * 32];          // [row][dh pair word]
__device__ unsigned g_Qtl[NROW * 32];
__device__ unsigned g_Kth[NROW * 32];
__device__ unsigned g_Ktl[NROW * 32];
__device__ unsigned g_Vth[B_ * 64 * 2048];     // [b][dh][kv pair word]
__device__ unsigned g_Vtl[B_ * 64 * 2048];
// partials: slot = ((b*32+qt)*8 + ch)
__device__ float g_po[1024 * 8192];
__device__ float g_pml[1024 * 256];
// W transposed K-major [3][64 h][1024 d], split hi/lo bf16 (proj)
__device__ __align__(16) unsigned short g_Wth[3 * 64 * 1024];
__device__ __align__(16) unsigned short g_Wtl[3 * 64 * 1024];

// round-to-nearest fp32 pair -> packed bf16 hi / lo-correction words
static __device__ __forceinline__ void split2(float a, float b,
                                              unsigned& h, unsigned& l) {
    unsigned ua = __float_as_uint(a), ub = __float_as_uint(b);
    unsigned ra = (ua + 0x7FFFu + ((ua >> 16) & 1u)) & 0xFFFF0000u;
    unsigned rb = (ub + 0x7FFFu + ((ub >> 16) & 1u)) & 0xFFFF0000u;
    h = (ra >> 16) | (rb & 0xFFFF0000u);
    float la = a - __uint_as_float(ra);
    float lb = b - __uint_as_float(rb);
    unsigned va = __float_as_uint(la), vb = __float_as_uint(lb);
    unsigned rla = (va + 0x7FFFu + ((va >> 16) & 1u));
    unsigned rlb = (vb + 0x7FFFu + ((vb >> 16) & 1u)) & 0xFFFF0000u;
    l = (rla >> 16) | rlb;
}

#define MMA_BF16(d, a0, a1, a2, a3, b0, b1)                                 \
    asm volatile("mma.sync.aligned.m16n8k16.row.col.f32.bf16.bf16.f32 "     \
        "{%0,%1,%2,%3}, {%4,%5,%6,%7}, {%8,%9}, {%0,%1,%2,%3};"             \
        : "+f"((d)[0]), "+f"((d)[1]), "+f"((d)[2]), "+f"((d)[3])            \
        : "r"(a0), "r"(a1), "r"(a2), "r"(a3), "r"(b0), "r"(b1))

// ---------------------------------------------------------------------------
// Kernel 0: W transpose + split (proj operand prep) — unchanged from R9.
// ---------------------------------------------------------------------------
__global__ __launch_bounds__(256) void wsplit_kernel(
    const float* __restrict__ Wq,
    const float* __restrict__ Wk,
    const float* __restrict__ Wv)
{
    const int mat = blockIdx.x;
    const int d0  = blockIdx.y * 64;
    const float* W = (mat == 0) ? Wq : (mat == 1) ? Wk : Wv;

    __shared__ float ts[64][65];
    const int tid = threadIdx.x;
    #pragma unroll
    for (int rep = 0; rep < 16; rep++) {
        int idx = rep * 256 + tid;
        ts[idx >> 6][idx & 63] = W[(size_t)(d0 + (idx >> 6)) * 64 + (idx & 63)];
    }
    __syncthreads();

    const int h  = tid >> 2;
    const int dg = (tid & 3) * 16;
    unsigned* oh = reinterpret_cast<unsigned*>(g_Wth);
    unsigned* ol = reinterpret_cast<unsigned*>(g_Wtl);
    #pragma unroll
    for (int j = 0; j < 8; j++) {
        unsigned hv, lv;
        split2(ts[dg + 2 * j][h], ts[dg + 2 * j + 1][h], hv, lv);
        int i32 = ((mat * 64 + h) * 1024 + d0 + dg + 2 * j) >> 1;
        oh[i32] = hv;
        ol[i32] = lv;
    }
}

// ---------------------------------------------------------------------------
// Kernel 1: QKV projection via mma.sync bf16 hi/lo — unchanged from R9.
// ---------------------------------------------------------------------------
#define SH 72

__global__ __launch_bounds__(256, 2) void proj_mma_kernel(
    const float* __restrict__ x)
{
    __shared__ unsigned short Ah[64 * SH], Al[64 * SH];
    __shared__ unsigned short Bh[64 * SH], Bl[64 * SH];

    const int tid  = threadIdx.x;
    const int wid  = tid >> 5, lane = tid & 31;
    const int g    = lane >> 2, tig = lane & 3;
    const int wm   = (wid & 3) * 16;
    const int wn   = (wid >> 2) * 32;
    const int mat  = blockIdx.y;
    const int row_base = blockIdx.x * 64;

    const unsigned short* Wh = g_Wth + (size_t)mat * 64 * 1024;
    const unsigned short* Wl = g_Wtl + (size_t)mat * 64 * 1024;

    const int lr = tid >> 2;
    const int lq = (tid & 3) * 16;

    float acc[4][4];
    #pragma unroll
    for (int nt = 0; nt < 4; nt++)
        #pragma unroll
        for (int r = 0; r < 4; r++) acc[nt][r] = 0.f;

    for (int c = 0; c < 16; c++) {
        const int k0 = c * 64;
        {
            const float4* xp = reinterpret_cast<const float4*>(
                x + (size_t)(row_base + lr) * D_ + k0 + lq);
            float4 v0 = xp[0], v1 = xp[1], v2 = xp[2], v3 = xp[3];
            uint4 hv, lv, hv2, lv2;
            split2(v0.x, v0.y, hv.x, lv.x);  split2(v0.z, v0.w, hv.y, lv.y);
            split2(v1.x, v1.y, hv.z, lv.z);  split2(v1.z, v1.w, hv.w, lv.w);
            split2(v2.x, v2.y, hv2.x, lv2.x); split2(v2.z, v2.w, hv2.y, lv2.y);
            split2(v3.x, v3.y, hv2.z, lv2.z); split2(v3.z, v3.w, hv2.w, lv2.w);
            unsigned short* pa = &Ah[lr * SH + lq];
            unsigned short* pl = &Al[lr * SH + lq];
            *reinterpret_cast<uint4*>(pa)     = hv;
            *reinterpret_cast<uint4*>(pa + 8) = hv2;
            *reinterpret_cast<uint4*>(pl)     = lv;
            *reinterpret_cast<uint4*>(pl + 8) = lv2;
        }
        {
            const uint4* bh = reinterpret_cast<const uint4*>(
                Wh + (size_t)lr * 1024 + k0 + lq);
            const uint4* bl = reinterpret_cast<const uint4*>(
                Wl + (size_t)lr * 1024 + k0 + lq);
            unsigned short* pb = &Bh[lr * SH + lq];
            unsigned short* pl = &Bl[lr * SH + lq];
            *reinterpret_cast<uint4*>(pb)     = bh[0];
            *reinterpret_cast<uint4*>(pb + 8) = bh[1];
            *reinterpret_cast<uint4*>(pl)     = bl[0];
            *reinterpret_cast<uint4*>(pl + 8) = bl[1];
        }
        __syncthreads();

        #pragma unroll
        for (int ks = 0; ks < 4; ks++) {
            const int wb = ks * 8;
            const int ra = (wm + g) * SH;
            unsigned ah0 = *reinterpret_cast<const unsigned*>(&Ah[ra + (wb + tig) * 2]);
            unsigned ah1 = *reinterpret_cast<const unsigned*>(&Ah[ra + 8 * SH + (wb + tig) * 2]);
            unsigned ah2 = *reinterpret_cast<const unsigned*>(&Ah[ra + (wb + 4 + tig) * 2]);
            unsigned ah3 = *reinterpret_cast<const unsigned*>(&Ah[ra + 8 * SH + (wb + 4 + tig) * 2]);
            unsigned al0 = *reinterpret_cast<const unsigned*>(&Al[ra + (wb + tig) * 2]);
            unsigned al1 = *reinterpret_cast<const unsigned*>(&Al[ra + 8 * SH + (wb + tig) * 2]);
            unsigned al2 = *reinterpret_cast<const unsigned*>(&Al[ra + (wb + 4 + tig) * 2]);
            unsigned al3 = *reinterpret_cast<const unsigned*>(&Al[ra + 8 * SH + (wb + 4 + tig) * 2]);

            #pragma unroll
            for (int nt = 0; nt < 4; nt++) {
                const int rb = (wn + nt * 8 + g) * SH;
                unsigned bh0 = *reinterpret_cast<const unsigned*>(&Bh[rb + (wb + tig) * 2]);
                unsigned bh1 = *reinterpret_cast<const unsigned*>(&Bh[rb + (wb + 4 + tig) * 2]);
                unsigned bl0 = *reinterpret_cast<const unsigned*>(&Bl[rb + (wb + tig) * 2]);
                unsigned bl1 = *reinterpret_cast<const unsigned*>(&Bl[rb + (wb + 4 + tig) * 2]);
                MMA_BF16(acc[nt], ah0, ah1, ah2, ah3, bh0, bh1);
                MMA_BF16(acc[nt], ah0, ah1, ah2, ah3, bl0, bl1);
                MMA_BF16(acc[nt], al0, al1, al2, al3, bh0, bh1);
            }
        }
        __syncthreads();
    }

    float* op = (mat == 0) ? g_Q : (mat == 1) ? g_K : g_V;
    const int row0 = row_base + wm + g;
    #pragma unroll
    for (int nt = 0; nt < 4; nt++) {
        const int col = wn + nt * 8 + 2 * tig;
        float2 v0 = make_float2(acc[nt][0], acc[nt][1]);
        float2 v1 = make_float2(acc[nt][2], acc[nt][3]);
        *reinterpret_cast<float2*>(&op[(size_t)row0 * DH_ + col])       = v0;
        *reinterpret_cast<float2*>(&op[(size_t)(row0 + 8) * DH_ + col]) = v1;
    }
}

// ---------------------------------------------------------------------------
// Kernel 1b: prep — split Q(*scale)/K to bf16 hi/lo pairs; V transposed.
// Grid 768: [0,256) V-transpose tiles, [256,512) Q, [512,768) K.
// ---------------------------------------------------------------------------
__global__ __launch_bounds__(256) void prep_kernel()
{
    const int bid = blockIdx.x, tid = threadIdx.x;

    if (bid < 256) {                     // V transpose: one 64-kv tile
        const int b = bid >> 6, t = bid & 63;
        __shared__ float ts[64][65];
        const float* src = g_V + ((size_t)(b * T_ + t * 64)) * 64;
        #pragma unroll
        for (int rep = 0; rep < 16; rep++) {
            int p = rep * 256 + tid;
            ts[p >> 6][p & 63] = src[p];
        }
        __syncthreads();
        const int d = tid >> 2, jg = (tid & 3) * 8;
        unsigned* oh = g_Vth + ((size_t)(b * 64 + d)) * 2048 + t * 32 + jg;
        unsigned* ol = g_Vtl + ((size_t)(b * 64 + d)) * 2048 + t * 32 + jg;
        #pragma unroll
        for (int j = 0; j < 8; j++) {
            int kvl = jg * 2 + 2 * j;
            unsigned h, l;
            split2(ts[kvl][d], ts[kvl + 1][d], h, l);
            oh[j] = h; ol[j] = l;
        }
    } else {                             // Q / K pack (row-major, dh pairs)
        const bool isQ = bid < 512;
        const int blk = bid - (isQ ? 256 : 512);
        const float sc = isQ ? 0.03125f : 1.0f;
        const float* src = isQ ? g_Q : g_K;
        unsigned* oh = isQ ? g_Qth : g_Kth;
        unsigned* ol = isQ ? g_Qtl : g_Ktl;
        const int r = blk * 64 + (tid >> 2);
        const int seg = (tid & 3) * 16;
        const float4* s4 = reinterpret_cast<const float4*>(
            src + (size_t)r * 64 + seg);
        unsigned* ph = oh + (size_t)r * 32 + (tid & 3) * 8;
        unsigned* pl = ol + (size_t)r * 32 + (tid & 3) * 8;
        #pragma unroll
        for (int j = 0; j < 4; j++) {
            float4 v = s4[j];
            unsigned h0, l0, h1, l1;
            split2(v.x * sc, v.y * sc, h0, l0);
            split2(v.z * sc, v.w * sc, h1, l1);
            ph[2 * j] = h0; ph[2 * j + 1] = h1;
            pl[2 * j] = l0; pl[2 * j + 1] = l1;
        }
    }
}

// ---------------------------------------------------------------------------
// Kernel 2: persistent flash attention on tensor cores (bf16 hi/lo mma).
// q-tile 128 rows, 8 warps x (16 rows x 64 kv). KV chunks of 8 tiles.
// ---------------------------------------------------------------------------
#define QW 36    // smem row stride in u32 words

__global__ __launch_bounds__(256, 2) void attn_kernel(float* __restrict__ out)
{
    extern __shared__ unsigned smw[];
    unsigned* Qh = smw;                         // 128*36
    unsigned* Ql = Qh + 128 * QW;
    unsigned* Kh = Ql + 128 * QW;               // 64*36
    unsigned* Kl = Kh + 64 * QW;
    unsigned* Vh = Kl + 64 * QW;
    unsigned* Vl = Vh + 64 * QW;
    __shared__ int s_item;

    const int tid = threadIdx.x;
    const int w = tid >> 5, lane = tid & 31;
    const int g = lane >> 2, tig = lane & 3;

    for (;;) {
        if (tid == 0) s_item = atomicAdd(&g_ctr, 1);
        __syncthreads();
        const int n = s_item;
        if (n >= NITEM) return;
        const int b = n & 3;
        int rem = n >> 2;                 // 0..143, ascending -> qt descending
        int qt = 31;
        while (rem >= ((2 * qt + 9) >> 3)) { rem -= (2 * qt + 9) >> 3; qt--; }
        const int ch = rem;
        const int nc = (2 * qt + 9) >> 3;
        const int t0 = ch * 8;
        const int tmax = 2 * qt + 2;
        const int t1 = (t0 + 8 < tmax) ? (t0 + 8) : tmax;

        // stage Q tile (pre-split bf16 pairs)
        {
            const int r = tid >> 1, seg = (tid & 1) * 16;
            const uint4* sh = reinterpret_cast<const uint4*>(
                g_Qth + ((size_t)(b * T_ + qt * 128 + r)) * 32 + seg);
            const uint4* sl = reinterpret_cast<const uint4*>(
                g_Qtl + ((size_t)(b * T_ + qt * 128 + r)) * 32 + seg);
            uint4* dh = reinterpret_cast<uint4*>(Qh + r * QW + seg);
            uint4* dl = reinterpret_cast<uint4*>(Ql + r * QW + seg);
            #pragma unroll
            for (int j = 0; j < 4; j++) { dh[j] = sh[j]; dl[j] = sl[j]; }
        }

        float o[8][4];
        float m0 = -INFINITY, m1 = -INFINITY, l0 = 0.f, l1 = 0.f;
        #pragma unroll
        for (int nt = 0; nt < 8; nt++)
            #pragma unroll
            for (int r = 0; r < 4; r++) o[nt][r] = 0.f;
        __syncthreads();

        const int r0g = qt * 128 + 16 * w + g;
        const int r1g = r0g + 8;

        for (int t = t0; t < t1; t++) {
            // stage K, V tiles (pure copies)
            {
                const int r = tid >> 2, seg = (tid & 3) * 8;
                const uint4* skh = reinterpret_cast<const uint4*>(
                    g_Kth + ((size_t)(b * T_ + t * 64 + r)) * 32 + seg);
                const uint4* skl = reinterpret_cast<const uint4*>(
                    g_Ktl + ((size_t)(b * T_ + t * 64 + r)) * 32 + seg);
                uint4* dkh = reinterpret_cast<uint4*>(Kh + r * QW + seg);
                uint4* dkl = reinterpret_cast<uint4*>(Kl + r * QW + seg);
                dkh[0] = skh[0]; dkh[1] = skh[1];
                dkl[0] = skl[0]; dkl[1] = skl[1];
                const uint4* svh = reinterpret_cast<const uint4*>(
                    g_Vth + ((size_t)(b * 64 + r)) * 2048 + t * 32 + seg);
                const uint4* svl = reinterpret_cast<const uint4*>(
                    g_Vtl + ((size_t)(b * 64 + r)) * 2048 + t * 32 + seg);
                uint4* dvh = reinterpret_cast<uint4*>(Vh + r * QW + seg);
                uint4* dvl = reinterpret_cast<uint4*>(Vl + r * QW + seg);
                dvh[0] = svh[0]; dvh[1] = svh[1];
                dvl[0] = svl[0]; dvl[1] = svl[1];
            }
            __syncthreads();

            // ---- S = Q K^T ----
            float s[8][4];
            #pragma unroll
            for (int nt = 0; nt < 8; nt++)
                #pragma unroll
                for (int r = 0; r < 4; r++) s[nt][r] = 0.f;

            #pragma unroll
            for (int ks = 0; ks < 4; ks++) {
                const int qa = (16 * w + g) * QW + 8 * ks + tig;
                unsigned ah0 = Qh[qa], ah1 = Qh[qa + 8 * QW];
                unsigned ah2 = Qh[qa + 4], ah3 = Qh[qa + 8 * QW + 4];
                unsigned al0 = Ql[qa], al1 = Ql[qa + 8 * QW];
                unsigned al2 = Ql[qa + 4], al3 = Ql[qa + 8 * QW + 4];
                #pragma unroll
                for (int nt = 0; nt < 8; nt++) {
                    const int kb = (8 * nt + g) * QW + 8 * ks + tig;
                    unsigned bh0 = Kh[kb], bh1 = Kh[kb + 4];
                    unsigned bl0 = Kl[kb], bl1 = Kl[kb + 4];
                    MMA_BF16(s[nt], ah0, ah1, ah2, ah3, bh0, bh1);
                    MMA_BF16(s[nt], ah0, ah1, ah2, ah3, bl0, bl1);
                    MMA_BF16(s[nt], al0, al1, al2, al3, bh0, bh1);
                }
            }

            // ---- causal mask (only near diagonal) ----
            if (t >= 2 * qt) {
                #pragma unroll
                for (int nt = 0; nt < 8; nt++) {
                    const int cb = t * 64 + 8 * nt + 2 * tig;
                    if (cb     > r0g) s[nt][0] = -1e30f;
                    if (cb + 1 > r0g) s[nt][1] = -1e30f;
                    if (cb     > r1g) s[nt][2] = -1e30f;
                    if (cb + 1 > r1g) s[nt][3] = -1e30f;
                }
            }

            // ---- online softmax (rows quad-local) ----
            float mt0 = -INFINITY, mt1 = -INFINITY;
            #pragma unroll
            for (int nt = 0; nt < 8; nt++) {
                mt0 = fmaxf(mt0, fmaxf(s[nt][0], s[nt][1]));
                mt1 = fmaxf(mt1, fmaxf(s[nt][2], s[nt][3]));
            }
            mt0 = fmaxf(mt0, __shfl_xor_sync(0xffffffffu, mt0, 1));
            mt0 = fmaxf(mt0, __shfl_xor_sync(0xffffffffu, mt0, 2));
            mt1 = fmaxf(mt1, __shfl_xor_sync(0xffffffffu, mt1, 1));
            mt1 = fmaxf(mt1, __shfl_xor_sync(0xffffffffu, mt1, 2));

            const float mn0 = fmaxf(m0, mt0), mn1 = fmaxf(m1, mt1);
            const float al = __expf(m0 - mn0), be = __expf(m1 - mn1);
            m0 = mn0; m1 = mn1;

            float rs0 = 0.f, rs1 = 0.f;
            #pragma unroll
            for (int nt = 0; nt < 8; nt++) {
                s[nt][0] = __expf(s[nt][0] - mn0);
                s[nt][1] = __expf(s[nt][1] - mn0);
                s[nt][2] = __expf(s[nt][2] - mn1);
                s[nt][3] = __expf(s[nt][3] - mn1);
                rs0 += s[nt][0] + s[nt][1];
                rs1 += s[nt][2] + s[nt][3];
                o[nt][0] *= al; o[nt][1] *= al;
                o[nt][2] *= be; o[nt][3] *= be;
            }
            rs0 += __shfl_xor_sync(0xffffffffu, rs0, 1);
            rs0 += __shfl_xor_sync(0xffffffffu, rs0, 2);
            rs1 += __shfl_xor_sync(0xffffffffu, rs1, 1);
            rs1 += __shfl_xor_sync(0xffffffffu, rs1, 2);
            l0 = l0 * al + rs0;
            l1 = l1 * be + rs1;

            // ---- O += P V (P in registers, hi/lo split) ----
            #pragma unroll
            for (int ks = 0; ks < 4; ks++) {
                unsigned ph0, pl0, ph1, pl1, ph2, pl2, ph3, pl3;
                split2(s[2 * ks][0],     s[2 * ks][1],     ph0, pl0);
                split2(s[2 * ks][2],     s[2 * ks][3],     ph1, pl1);
                split2(s[2 * ks + 1][0], s[2 * ks + 1][1], ph2, pl2);
                split2(s[2 * ks + 1][2], s[2 * ks + 1][3], ph3, pl3);
                #pragma unroll
                for (int nt = 0; nt < 8; nt++) {
                    const int vb = (8 * nt + g) * QW + 8 * ks + tig;
                    unsigned bh0 = Vh[vb], bh1 = Vh[vb + 4];
                    unsigned bl0 = Vl[vb], bl1 = Vl[vb + 4];
                    MMA_BF16(o[nt], ph0, ph1, ph2, ph3, bh0, bh1);
                    MMA_BF16(o[nt], ph0, ph1, ph2, ph3, bl0, bl1);
                    MMA_BF16(o[nt], pl0, pl1, pl2, pl3, bh0, bh1);
                }
            }
            __syncthreads();
        }

        // ---- epilogue ----
        if (nc == 1) {
            const float i0 = 1.0f / l0, i1 = 1.0f / l1;
            float* og = out + (size_t)(b * T_) * DH_;
            #pragma unroll
            for (int nt = 0; nt < 8; nt++) {
                const int col = 8 * nt + 2 * tig;
                *reinterpret_cast<float2*>(&og[(size_t)r0g * DH_ + col]) =
                    make_float2(o[nt][0] * i0, o[nt][1] * i0);
                *reinterpret_cast<float2*>(&og[(size_t)r1g * DH_ + col]) =
                    make_float2(o[nt][2] * i1, o[nt][3] * i1);
            }
        } else {
            const int pidx = (b * 32 + qt) * 8 + ch;
            float* po = g_po + (size_t)pidx * 8192;
            const int rr0 = 16 * w + g, rr1 = rr0 + 8;
            #pragma unroll
            for (int nt = 0; nt < 8; nt++) {
                const int col = 8 * nt + 2 * tig;
                *reinterpret_cast<float2*>(&po[rr0 * 64 + col]) =
                    make_float2(o[nt][0], o[nt][1]);
                *reinterpret_cast<float2*>(&po[rr1 * 64 + col]) =
                    make_float2(o[nt][2], o[nt][3]);
            }
            if (tig == 0) {
                g_pml[pidx * 256 + rr0]       = m0;
                g_pml[pidx * 256 + 128 + rr0] = l0;
                g_pml[pidx * 256 + rr1]       = m1;
                g_pml[pidx * 256 + 128 + rr1] = l1;
            }
        }
    }
}

// ---------------------------------------------------------------------------
// Kernel 3: merge partials (qt >= 4) + reset queue. Grid 112.
// ---------------------------------------------------------------------------
__global__ __launch_bounds__(256) void merge_kernel(float* __restrict__ out)
{
    if (blockIdx.x == 0 && threadIdx.x == 0) g_ctr = 0;

    const int bid = blockIdx.x;
    const int b  = bid & 3;
    const int qt = 4 + (bid >> 2);
    const int nc = (2 * qt + 9) >> 3;     // 2..8
    const int tid = threadIdx.x;
    const int r  = tid >> 1;
    const int cg = (tid & 1) * 32;

    const int base = (b * 32 + qt) * 8;

    float mv[8], lv[8];
    float ms = -INFINITY;
    for (int c = 0; c < nc; c++) {
        mv[c] = g_pml[(base + c) * 256 + r];
        lv[c] = g_pml[(base + c) * 256 + 128 + r];
        ms = fmaxf(ms, mv[c]);
    }

    float acc[32];
    #pragma unroll
    for (int j = 0; j < 32; j++) acc[j] = 0.f;
    float lsum = 0.f;

    for (int c = 0; c < nc; c++) {
        const float wgt = __expf(mv[c] - ms);
        lsum += lv[c] * wgt;
        const float* po = g_po + (size_t)(base + c) * 8192 + r * 64 + cg;
        #pragma unroll
        for (int j4 = 0; j4 < 8; j4++) {
            float4 v = *reinterpret_cast<const float4*>(po + j4 * 4);
            acc[j4 * 4 + 0] = fmaf(v.x, wgt, acc[j4 * 4 + 0]);
            acc[j4 * 4 + 1] = fmaf(v.y, wgt, acc[j4 * 4 + 1]);
            acc[j4 * 4 + 2] = fmaf(v.z, wgt, acc[j4 * 4 + 2]);
            acc[j4 * 4 + 3] = fmaf(v.w, wgt, acc[j4 * 4 + 3]);
        }
    }

    const float inv = 1.0f / lsum;
    float* og = out + (size_t)(b * T_ + qt * 128 + r) * DH_ + cg;
    #pragma unroll
    for (int j4 = 0; j4 < 8; j4++) {
        float4 v;
        v.x = acc[j4 * 4 + 0] * inv;
        v.y = acc[j4 * 4 + 1] * inv;
        v.z = acc[j4 * 4 + 2] * inv;
        v.w = acc[j4 * 4 + 3] * inv;
        *reinterpret_cast<float4*>(og + j4 * 4) = v;
    }
}

// ---------------------------------------------------------------------------
extern "C" void kernel_launch(void* const* d_in, const int* in_sizes, int n_in,
                              void* d_out, int out_size)
{
    const float* x  = (const float*)d_in[0];
    const float* Wq = (const float*)d_in[1];
    const float* Wk = (const float*)d_in[2];
    const float* Wv = (const float*)d_in[3];
    float* out = (float*)d_out;

    dim3 gw(3, 16);
    wsplit_kernel<<<gw, 256>>>(Wq, Wk, Wv);

    dim3 gp(256, 3);
    proj_mma_kernel<<<gp, 256>>>(x);

    prep_kernel<<<768, 256>>>();

    const int asmem = (128 * 2 + 64 * 4) * QW * 4;   // 73728 B
    cudaFuncSetAttribute(attn_kernel,
                         cudaFuncAttributeMaxDynamicSharedMemorySize, asmem);
    attn_kernel<<<296, 256, asmem>>>(out);

    merge_kernel<<<112, 256>>>(out);
}